// round 10
// baseline (speedup 1.0000x reference)
#include <cuda_runtime.h>
#include <cuda_fp16.h>
#include <cuda_bf16.h>
#include <math.h>
#include <stdint.h>

// ---------------------------------------------------------------------------
// Wav2VecFeats on sm_100: conv1..6 via HMMA m16n8k16 fp16 (fp32 accum).
// Intermediates as 3 half planes [c][{even,odd,even+1}][u].
// R9: pre-shifted plane2 (no funnel pass), 1 barrier/chunk, conv0-fused stats.
// ---------------------------------------------------------------------------

#define BB 8
#define CC 512
#define L0 40000
#define T0 7999
#define T1 3999
#define T2 1999
#define T3 999
#define T4 499
#define T5 249
#define T6 124

#define HP1 4008
#define HP2 2056

typedef unsigned long long u64;

__device__ float  g_bufA[BB * CC * T0];                       // fp32 scratch
__device__ __half g_H1[(size_t)BB * CC * 3 * HP1 + 8192];
__device__ __half g_H2[(size_t)BB * CC * 3 * HP2 + 8192];
__device__ __half g_wrh[4194304];
__device__ float  g_sum[2][BB * CC];
__device__ float  g_coef[2][BB * CC];

__device__ __forceinline__ float gelu_tanh(float x) {
    const float c0 = 0.7978845608028654f;
    const float c1 = 0.044715f;
    float x3 = x * x * x;
    float t = tanhf(c0 * (x + c1 * x3));
    return 0.5f * x * (1.0f + t);
}

__device__ __forceinline__ uint32_t smem_u32(const void* p) {
    uint32_t a;
    asm("{ .reg .u64 t; cvta.to.shared.u64 t, %1; cvt.u32.u64 %0, t; }"
        : "=r"(a) : "l"(p));
    return a;
}
__device__ __forceinline__ void cp_async16(void* dst, const void* src) {
    asm volatile("cp.async.ca.shared.global [%0], [%1], 16;"
                 :: "r"(smem_u32(dst)), "l"(src));
}
__device__ __forceinline__ void cp_commit() {
    asm volatile("cp.async.commit_group;" ::: "memory");
}
template<int N> __device__ __forceinline__ void cp_wait() {
    asm volatile("cp.async.wait_group %0;" :: "n"(N) : "memory");
}

__device__ __forceinline__ void mma_f16(float* d, const uint32_t* a,
                                        uint32_t b0, uint32_t b1) {
    asm volatile(
        "mma.sync.aligned.m16n8k16.row.col.f32.f16.f16.f32 "
        "{%0,%1,%2,%3}, {%4,%5,%6,%7}, {%8,%9}, {%0,%1,%2,%3};"
        : "+f"(d[0]), "+f"(d[1]), "+f"(d[2]), "+f"(d[3])
        : "r"(a[0]), "r"(a[1]), "r"(a[2]), "r"(a[3]), "r"(b0), "r"(b1));
}
__device__ __forceinline__ void ldmx2t(uint32_t& b0, uint32_t& b1, uint32_t addr) {
    asm volatile("ldmatrix.sync.aligned.m8n8.x2.trans.shared.b16 {%0,%1}, [%2];"
                 : "=r"(b0), "=r"(b1) : "r"(addr));
}

// ---------------------------------------------------------------------------
// zero the stats accumulators (graph-replay safe)
// ---------------------------------------------------------------------------
__global__ void zero_stats_kernel() {
    int i = blockIdx.x * 256 + threadIdx.x;
    if (i < BB * CC) { g_sum[0][i] = 0.0f; g_sum[1][i] = 0.0f; }
}

// ---------------------------------------------------------------------------
// conv0: (B,40000) -> (B,512,7999) fp32 raw + per-(b,c) sum / sumsq
// ---------------------------------------------------------------------------
#define C0_TT 128
__global__ __launch_bounds__(256) void conv0_kernel(
    const float* __restrict__ x, const float* __restrict__ w,
    float* __restrict__ out)
{
    __shared__ float sx[5 * C0_TT + 10];
    __shared__ float sw[CC * 10];
    __shared__ float s_s[CC], s_s2[CC];
    const int b = blockIdx.y;
    const int t0 = blockIdx.x * C0_TT;
    const int tid = threadIdx.x;
    const int lane = tid & 31;

    for (int i = tid; i < CC * 10; i += 256) sw[i] = w[i];
    for (int i = tid; i < CC; i += 256) { s_s[i] = 0.0f; s_s2[i] = 0.0f; }
    for (int i = tid; i < 5 * C0_TT + 10; i += 256) {
        int gi = 5 * t0 + i;
        sx[i] = (gi < L0) ? x[b * L0 + gi] : 0.0f;
    }
    __syncthreads();

    for (int idx = tid; idx < CC * C0_TT; idx += 256) {
        int tl = idx & (C0_TT - 1);
        int c  = idx >> 7;                   // warp-uniform
        int t  = t0 + tl;
        float acc = 0.0f;
        const float* wc = &sw[c * 10];
        const float* xp = &sx[5 * tl];
        #pragma unroll
        for (int j = 0; j < 10; ++j) acc = fmaf(wc[j], xp[j], acc);
        bool valid = (t < T0);
        if (valid) out[(b * CC + c) * T0 + t] = acc;
        float s1 = valid ? acc : 0.0f;
        float s2 = s1 * acc;
        #pragma unroll
        for (int off = 16; off > 0; off >>= 1) {
            s1 += __shfl_down_sync(0xffffffffu, s1, off);
            s2 += __shfl_down_sync(0xffffffffu, s2, off);
        }
        if (lane == 0) {
            atomicAdd(&s_s[c], s1);
            atomicAdd(&s_s2[c], s2);
        }
    }
    __syncthreads();
    for (int i = tid; i < CC; i += 256) {
        atomicAdd(&g_sum[0][b * CC + i], s_s[i]);
        atomicAdd(&g_sum[1][b * CC + i], s_s2[i]);
    }
}

// ---------------------------------------------------------------------------
// stats -> per-(b,c) affine coefficients
// ---------------------------------------------------------------------------
__global__ void stats_kernel(const float* __restrict__ scale,
                             const float* __restrict__ bias) {
    int i = blockIdx.x * 256 + threadIdx.x;
    if (i < BB * CC) {
        int c = i & (CC - 1);
        float mean = g_sum[0][i] * (1.0f / T0);
        float var  = g_sum[1][i] * (1.0f / T0) - mean * mean;
        float inv  = rsqrtf(var + 1e-5f);
        float a = scale[c] * inv;
        g_coef[0][i] = a;
        g_coef[1][i] = bias[c] - mean * a;
    }
}

// ---------------------------------------------------------------------------
// apply norm+gelu -> 3 half planes
// ---------------------------------------------------------------------------
__global__ __launch_bounds__(256) void apply_kernel(
    const float* __restrict__ h, __half* __restrict__ outH)
{
    const int bc = blockIdx.y * CC + blockIdx.x;
    const int tid = threadIdx.x;
    const float* p = h + (size_t)bc * T0;
    float a = g_coef[0][bc];
    float d = g_coef[1][bc];
    __half* ob = outH + (size_t)bc * 3 * HP1;
    for (int i = tid; i < 8008; i += 256) {
        float v = (i < T0) ? gelu_tanh(fmaf(p[i], a, d)) : 0.0f;
        __half hv = __float2half_rn(v);
        int u = i >> 1;
        if (i & 1) ob[HP1 + u] = hv;
        else {
            ob[u] = hv;
            if (u >= 1) ob[2 * HP1 + u - 1] = hv;
        }
    }
}

// ---------------------------------------------------------------------------
// Weight prep (all 6 layers, one launch): fp16 + m16n8k16 A-fragment order.
// ---------------------------------------------------------------------------
__global__ __launch_bounds__(256) void wprep_kernel(
    const float* __restrict__ s1, const float* __restrict__ s2,
    const float* __restrict__ s3, const float* __restrict__ s4,
    const float* __restrict__ s5, const float* __restrict__ s6,
    __half* __restrict__ dstAll)
{
    const int ly = blockIdx.y;
    const float* src = (ly == 0) ? s1 : (ly == 1) ? s2 : (ly == 2) ? s3 :
                       (ly == 3) ? s4 : (ly == 4) ? s5 : s6;
    const int K = (ly < 4) ? 3 : 2;
    size_t base = (ly <= 4) ? (size_t)ly * 786432 : (4u * 786432 + 524288);
    __half* dst = dstAll + base;
    const int total = K * 262144;

    for (int d = blockIdx.x * 256 + threadIdx.x; d < total; d += gridDim.x * 256) {
        int hh   = d & 7;
        int lane = (d >> 3) & 31;
        int cb   = (d >> 8) & 31;
        int kc   = (d >> 13) & 31;
        int j    = d >> 18;
        int q = lane >> 2, r4 = lane & 3;
        int ph = hh >> 1, off = hh & 1;
        int m = q + ((ph & 1) ? 8 : 0);
        int k = 2 * r4 + off + ((ph & 2) ? 8 : 0);
        int co = cb * 16 + m;
        int ci = kc * 16 + k;
        dst[d] = __float2half_rn(src[(size_t)(co * 512 + ci) * K + j]);
    }
}

// ---------------------------------------------------------------------------
// fp16 HMMA conv layer. CTA 128co x NT t, 8 warps (2 x 4), warp 64 x NT/4.
// 3-stage cp.async pipeline, one barrier per chunk, K aligned planes.
// ---------------------------------------------------------------------------
template<int K, int NT, bool F32OUT>
__global__ __launch_bounds__(256, 1) void conv_hmma_kernel(
    const __half* __restrict__ inH, const __half* __restrict__ wh,
    void* __restrict__ outp, int HPin, int HPout, int Tout)
{
    constexpr int NTT  = NT / 32;
    constexpr int WU   = NT + 8;
    constexpr int ABY  = K * 4096;
    constexpr int PLB  = 16 * WU * 2;
    constexpr int STGB = ABY + K * PLB;
    constexpr int NSB  = K * NT / 128;         // B 16B-slots per thread

    extern __shared__ char smem[];

    const int tid = threadIdx.x;
    const int wrp = tid >> 5;
    const int l   = tid & 31;
    const int q   = l >> 2;
    const int r4  = l & 3;
    const int wm  = wrp & 1;
    const int wn  = wrp >> 1;
    const int tw  = wn * (NT / 4);

    const int b   = blockIdx.z;
    const int co0 = blockIdx.y * 128;
    const int cb0 = blockIdx.y * 8;
    const int t0  = blockIdx.x * NT;

    float acc[4][NTT][4];
    #pragma unroll
    for (int mt = 0; mt < 4; ++mt)
        #pragma unroll
        for (int nt = 0; nt < NTT; ++nt)
            #pragma unroll
            for (int e = 0; e < 4; ++e) acc[mt][nt][e] = 0.0f;

    // ---- precomputed staging slots --------------------------------------
    const __half* srcA[K];
    uint32_t dA[K];
    #pragma unroll
    for (int k = 0; k < K; ++k) {
        int i = tid + k * 256;
        int j = i >> 8, x = i & 255;
        dA[k] = j * 4096 + x * 16;
        srcA[k] = wh + (size_t)(j * 32 * 32 + cb0) * 256 + x * 8;
    }
    const __half* srcB[NSB];
    uint32_t dB[NSB];
    #pragma unroll
    for (int k = 0; k < NSB; ++k) {
        int i = tid + k * 256;
        int w, ci, p;
        if (NT == 256) { w = i & 31; ci = (i >> 5) & 15; p = i >> 9; }
        else           { w = i & 15; ci = (i >> 4) & 15; p = i >> 8; }
        dB[k] = ABY + p * PLB + ci * (WU * 2) + w * 16;
        srcB[k] = inH + ((size_t)(b * CC + ci) * 3 + p) * HPin + t0 + 8 * w;
    }

    uint32_t stI = 0;
    auto issue = [&]() {
        char* SB = smem + stI;
        #pragma unroll
        for (int k = 0; k < K; ++k) {
            cp_async16(SB + dA[k], srcA[k]);
            srcA[k] += 8192;
        }
        #pragma unroll
        for (int k = 0; k < NSB; ++k) {
            cp_async16(SB + dB[k], srcB[k]);
            srcB[k] += (size_t)48 * HPin;      // 16 channels * 3 planes
        }
        cp_commit();
        stI += STGB;
        if (stI == 3 * STGB) stI = 0;
    };

    issue();
    issue();

    const uint32_t smem_base_u = smem_u32(smem);
    uint32_t stC = 0;

    for (int c = 0; c < 32; ++c) {
        if (c < 31) cp_wait<1>(); else cp_wait<0>();
        __syncthreads();
        if (c < 30) issue();

        char* SB = smem + stC;
        const uint32_t su = smem_base_u + stC;

        #pragma unroll
        for (int j = 0; j < K; ++j) {
            uint4 af[4];
            #pragma unroll
            for (int mt = 0; mt < 4; ++mt)
                af[mt] = *(const uint4*)(SB + j * 4096 + (wm * 4 + mt) * 512 + l * 16);
            #pragma unroll
            for (int nt = 0; nt < NTT; ++nt) {
                uint32_t b0, b1;
                uint32_t baddr = su + ABY + j * PLB + (l & 15) * (WU * 2)
                               + (tw + 8 * nt) * 2;
                ldmx2t(b0, b1, baddr);
                #pragma unroll
                for (int mt = 0; mt < 4; ++mt)
                    mma_f16(acc[mt][nt], (const uint32_t*)&af[mt], b0, b1);
            }
        }

        stC += STGB;
        if (stC == 3 * STGB) stC = 0;
    }

    // ---- epilogue -------------------------------------------------------
    if (F32OUT) {
        float* ob = (float*)outp;
        #pragma unroll
        for (int mt = 0; mt < 4; ++mt) {
            int row0 = co0 + wm * 64 + 16 * mt + q;
            #pragma unroll
            for (int nt = 0; nt < NTT; ++nt) {
                int t = t0 + tw + 8 * nt + 2 * r4;
                float v0 = gelu_tanh(acc[mt][nt][0]);
                float v1 = gelu_tanh(acc[mt][nt][1]);
                float v2 = gelu_tanh(acc[mt][nt][2]);
                float v3 = gelu_tanh(acc[mt][nt][3]);
                if (t < Tout) {
                    ob[(size_t)(b * CC + row0) * Tout + t]     = v0;
                    ob[(size_t)(b * CC + row0 + 8) * Tout + t] = v2;
                }
                if (t + 1 < Tout) {
                    ob[(size_t)(b * CC + row0) * Tout + t + 1]     = v1;
                    ob[(size_t)(b * CC + row0 + 8) * Tout + t + 1] = v3;
                }
            }
        }
    } else {
        __half* oh = (__half*)outp;
        #pragma unroll
        for (int mt = 0; mt < 4; ++mt) {
            int row0 = co0 + wm * 64 + 16 * mt + q;
            size_t base0 = (size_t)(b * CC + row0) * 3 * HPout;
            size_t base8 = (size_t)(b * CC + row0 + 8) * 3 * HPout;
            #pragma unroll
            for (int nt = 0; nt < NTT; ++nt) {
                int t = t0 + tw + 8 * nt + 2 * r4;   // even
                int u = t >> 1;
                __half h0 = (t     < Tout) ? __float2half_rn(gelu_tanh(acc[mt][nt][0])) : __half(0.0f);
                __half h1 = (t + 1 < Tout) ? __float2half_rn(gelu_tanh(acc[mt][nt][1])) : __half(0.0f);
                __half h2 = (t     < Tout) ? __float2half_rn(gelu_tanh(acc[mt][nt][2])) : __half(0.0f);
                __half h3 = (t + 1 < Tout) ? __float2half_rn(gelu_tanh(acc[mt][nt][3])) : __half(0.0f);
                oh[base0 + u]          = h0;
                oh[base0 + HPout + u]  = h1;
                oh[base8 + u]          = h2;
                oh[base8 + HPout + u]  = h3;
                if (u >= 1) {
                    oh[base0 + 2 * HPout + u - 1] = h0;
                    oh[base8 + 2 * HPout + u - 1] = h2;
                }
            }
        }
    }
}

// ---------------------------------------------------------------------------
// Tail head (reads fp32 conv6 output)
// ---------------------------------------------------------------------------
__global__ __launch_bounds__(256) void tail_kernel(
    const float* __restrict__ h, const int* __restrict__ word_ids,
    const float* __restrict__ proj_w, const float* __restrict__ proj_b,
    const float* __restrict__ cls_w1, const float* __restrict__ cls_b1,
    const float* __restrict__ cls_w2, const float* __restrict__ cls_b2,
    float* __restrict__ out)
{
    const int b = blockIdx.x;
    const int tid = threadIdx.x;
    __shared__ float feat[CC];
    __shared__ float pr[256];
    __shared__ float h1[128];

    const float* hb = h + (size_t)b * CC * T6;
    for (int c = tid; c < CC; c += 256) {
        float s = 0.0f;
        const float* row = hb + (size_t)c * T6;
        for (int t = 0; t < T6; ++t) s += row[t];
        feat[c] = s * (1.0f / (float)T6);
    }
    __syncthreads();

    {
        float s = proj_b[tid];
        const float* wrow = proj_w + (size_t)tid * CC;
        for (int d = 0; d < CC; ++d) s = fmaf(wrow[d], feat[d], s);
        pr[tid] = fmaxf(s, 0.0f);
    }
    __syncthreads();

    const int wd = word_ids[b];
    if (tid < 128) {
        float s = cls_b1[wd * 128 + tid];
        const float* w1 = cls_w1 + (size_t)wd * 256 * 128;
        for (int d = 0; d < 256; ++d)
            s = fmaf(pr[d], w1[d * 128 + tid], s);
        h1[tid] = fmaxf(s, 0.0f);
    }
    __syncthreads();

    if (tid < 5) {
        float s = cls_b2[wd * 5 + tid];
        const float* w2 = cls_w2 + (size_t)wd * 128 * 5;
        for (int d = 0; d < 128; ++d)
            s = fmaf(h1[d], w2[d * 5 + tid], s);
        out[b * 5 + tid] = s;
    }
}

// ---------------------------------------------------------------------------
// Launch
// ---------------------------------------------------------------------------
extern "C" void kernel_launch(void* const* d_in, const int* in_sizes, int n_in,
                              void* d_out, int out_size)
{
    const float* x        = (const float*)d_in[0];
    const int*   word_ids = (const int*)  d_in[1];
    const float* gn_scale = (const float*)d_in[2];
    const float* gn_bias  = (const float*)d_in[3];
    const float* proj_w   = (const float*)d_in[4];
    const float* proj_b   = (const float*)d_in[5];
    const float* cls_w1   = (const float*)d_in[6];
    const float* cls_b1   = (const float*)d_in[7];
    const float* cls_w2   = (const float*)d_in[8];
    const float* cls_b2   = (const float*)d_in[9];
    const float* w0       = (const float*)d_in[10];
    const float* w1       = (const float*)d_in[11];
    const float* w2       = (const float*)d_in[12];
    const float* w3       = (const float*)d_in[13];
    const float* w4       = (const float*)d_in[14];
    const float* w5       = (const float*)d_in[15];
    const float* w6       = (const float*)d_in[16];
    float* out = (float*)d_out;

    float *bufA = nullptr;
    __half *H1 = nullptr, *H2 = nullptr, *wrh = nullptr;
    cudaGetSymbolAddress((void**)&bufA, g_bufA);
    cudaGetSymbolAddress((void**)&H1, g_H1);
    cudaGetSymbolAddress((void**)&H2, g_H2);
    cudaGetSymbolAddress((void**)&wrh, g_wrh);

    const size_t PL3 = 786432;
    __half* wr1 = wrh;
    __half* wr2 = wr1 + PL3;
    __half* wr3 = wr2 + PL3;
    __half* wr4 = wr3 + PL3;
    __half* wr5 = wr4 + PL3;
    __half* wr6 = wr5 + 524288;

    const int SM3_256 = 3 * (3 * 4096 + 3 * 16 * 264 * 2);   // 112896
    const int SM3_128 = 3 * (3 * 4096 + 3 * 16 * 136 * 2);   // 76032
    const int SM2_128 = 3 * (2 * 4096 + 2 * 16 * 136 * 2);   // 50688
    cudaFuncSetAttribute((const void*)conv_hmma_kernel<3, 256, false>,
                         cudaFuncAttributeMaxDynamicSharedMemorySize, SM3_256);
    cudaFuncSetAttribute((const void*)conv_hmma_kernel<3, 128, false>,
                         cudaFuncAttributeMaxDynamicSharedMemorySize, SM3_128);
    cudaFuncSetAttribute((const void*)conv_hmma_kernel<2, 128, false>,
                         cudaFuncAttributeMaxDynamicSharedMemorySize, SM2_128);
    cudaFuncSetAttribute((const void*)conv_hmma_kernel<2, 128, true>,
                         cudaFuncAttributeMaxDynamicSharedMemorySize, SM2_128);

    zero_stats_kernel<<<32, 256>>>();
    wprep_kernel<<<dim3(96, 6), 256>>>(w1, w2, w3, w4, w5, w6, wrh);
    conv0_kernel<<<dim3((T0 + C0_TT - 1) / C0_TT, BB), 256>>>(x, w0, bufA);
    stats_kernel<<<32, 256>>>(gn_scale, gn_bias);
    apply_kernel<<<dim3(CC, BB), 256>>>(bufA, H1);

    conv_hmma_kernel<3, 256, false><<<dim3(16, 4, BB), 256, SM3_256>>>(
        H1, wr1, H2, HP1, HP2, T1);
    conv_hmma_kernel<3, 256, false><<<dim3(8, 4, BB), 256, SM3_256>>>(
        H2, wr2, H1, HP2, HP1, T2);
    conv_hmma_kernel<3, 256, false><<<dim3(4, 4, BB), 256, SM3_256>>>(
        H1, wr3, H2, HP1, HP2, T3);
    conv_hmma_kernel<3, 128, false><<<dim3(4, 4, BB), 256, SM3_128>>>(
        H2, wr4, H1, HP2, HP1, T4);
    conv_hmma_kernel<2, 128, false><<<dim3(2, 4, BB), 256, SM2_128>>>(
        H1, wr5, H2, HP1, HP2, T5);
    conv_hmma_kernel<2, 128, true><<<dim3(1, 4, BB), 256, SM2_128>>>(
        H2, wr6, bufA, HP2, 0, T6);

    tail_kernel<<<BB, 256>>>(bufA, word_ids, proj_w, proj_b,
                             cls_w1, cls_b1, cls_w2, cls_b2, out);
}

// round 11
// speedup vs baseline: 1.1127x; 1.1127x over previous
#include <cuda_runtime.h>
#include <cuda_fp16.h>
#include <cuda_bf16.h>
#include <math.h>
#include <stdint.h>

// ---------------------------------------------------------------------------
// Wav2VecFeats on sm_100: conv1..6 via HMMA m16n8k16 fp16 (fp32 accum).
// Intermediates as 2 half parity planes [c][t&1][u]; j=2 plane built in smem.
// R11: NT=128 + 2 CTAs/SM (occ 25%), 2 barriers/chunk, fused gn stats kept.
// ---------------------------------------------------------------------------

#define BB 8
#define CC 512
#define L0 40000
#define T0 7999
#define T1 3999
#define T2 1999
#define T3 999
#define T4 499
#define T5 249
#define T6 124

#define HP1 4008
#define HP2 2056

typedef unsigned long long u64;

__device__ float  g_bufA[BB * CC * T0];                     // fp32 scratch
__device__ __half g_H1[(size_t)BB * CC * 2 * HP1 + 8192];   // padded
__device__ __half g_H2[(size_t)BB * CC * 2 * HP2 + 8192];   // padded
__device__ __half g_wrh[4194304];                           // frag-packed weights
__device__ float  g_sum[2][BB * CC];
__device__ float  g_coef[2][BB * CC];

__device__ __forceinline__ float gelu_tanh(float x) {
    const float c0 = 0.7978845608028654f;
    const float c1 = 0.044715f;
    float x3 = x * x * x;
    float t = tanhf(c0 * (x + c1 * x3));
    return 0.5f * x * (1.0f + t);
}

__device__ __forceinline__ uint32_t smem_u32(const void* p) {
    uint32_t a;
    asm("{ .reg .u64 t; cvta.to.shared.u64 t, %1; cvt.u32.u64 %0, t; }"
        : "=r"(a) : "l"(p));
    return a;
}
__device__ __forceinline__ void cp_async16(void* dst, const void* src) {
    asm volatile("cp.async.ca.shared.global [%0], [%1], 16;"
                 :: "r"(smem_u32(dst)), "l"(src));
}
__device__ __forceinline__ void cp_async4(void* dst, const void* src) {
    asm volatile("cp.async.ca.shared.global [%0], [%1], 4;"
                 :: "r"(smem_u32(dst)), "l"(src));
}
__device__ __forceinline__ void cp_commit() {
    asm volatile("cp.async.commit_group;" ::: "memory");
}
template<int N> __device__ __forceinline__ void cp_wait() {
    asm volatile("cp.async.wait_group %0;" :: "n"(N) : "memory");
}

__device__ __forceinline__ void mma_f16(float* d, const uint32_t* a,
                                        uint32_t b0, uint32_t b1) {
    asm volatile(
        "mma.sync.aligned.m16n8k16.row.col.f32.f16.f16.f32 "
        "{%0,%1,%2,%3}, {%4,%5,%6,%7}, {%8,%9}, {%0,%1,%2,%3};"
        : "+f"(d[0]), "+f"(d[1]), "+f"(d[2]), "+f"(d[3])
        : "r"(a[0]), "r"(a[1]), "r"(a[2]), "r"(a[3]), "r"(b0), "r"(b1));
}
__device__ __forceinline__ void ldmx2t(uint32_t& b0, uint32_t& b1, uint32_t addr) {
    asm volatile("ldmatrix.sync.aligned.m8n8.x2.trans.shared.b16 {%0,%1}, [%2];"
                 : "=r"(b0), "=r"(b1) : "r"(addr));
}

// ---------------------------------------------------------------------------
// zero the stats accumulators (graph-replay safe)
// ---------------------------------------------------------------------------
__global__ void zero_stats_kernel() {
    int i = blockIdx.x * 256 + threadIdx.x;
    if (i < BB * CC) { g_sum[0][i] = 0.0f; g_sum[1][i] = 0.0f; }
}

// ---------------------------------------------------------------------------
// conv0: (B,40000) -> (B,512,7999) fp32 raw + per-(b,c) sum / sumsq
// ---------------------------------------------------------------------------
#define C0_TT 128
__global__ __launch_bounds__(256) void conv0_kernel(
    const float* __restrict__ x, const float* __restrict__ w,
    float* __restrict__ out)
{
    __shared__ float sx[5 * C0_TT + 10];
    __shared__ float sw[CC * 10];
    __shared__ float s_s[CC], s_s2[CC];
    const int b = blockIdx.y;
    const int t0 = blockIdx.x * C0_TT;
    const int tid = threadIdx.x;
    const int lane = tid & 31;

    for (int i = tid; i < CC * 10; i += 256) sw[i] = w[i];
    for (int i = tid; i < CC; i += 256) { s_s[i] = 0.0f; s_s2[i] = 0.0f; }
    for (int i = tid; i < 5 * C0_TT + 10; i += 256) {
        int gi = 5 * t0 + i;
        sx[i] = (gi < L0) ? x[b * L0 + gi] : 0.0f;
    }
    __syncthreads();

    for (int idx = tid; idx < CC * C0_TT; idx += 256) {
        int tl = idx & (C0_TT - 1);
        int c  = idx >> 7;                   // warp-uniform
        int t  = t0 + tl;
        float acc = 0.0f;
        const float* wc = &sw[c * 10];
        const float* xp = &sx[5 * tl];
        #pragma unroll
        for (int j = 0; j < 10; ++j) acc = fmaf(wc[j], xp[j], acc);
        bool valid = (t < T0);
        if (valid) out[(b * CC + c) * T0 + t] = acc;
        float s1 = valid ? acc : 0.0f;
        float s2 = s1 * acc;
        #pragma unroll
        for (int off = 16; off > 0; off >>= 1) {
            s1 += __shfl_down_sync(0xffffffffu, s1, off);
            s2 += __shfl_down_sync(0xffffffffu, s2, off);
        }
        if (lane == 0) {
            atomicAdd(&s_s[c], s1);
            atomicAdd(&s_s2[c], s2);
        }
    }
    __syncthreads();
    for (int i = tid; i < CC; i += 256) {
        atomicAdd(&g_sum[0][b * CC + i], s_s[i]);
        atomicAdd(&g_sum[1][b * CC + i], s_s2[i]);
    }
}

// ---------------------------------------------------------------------------
// stats -> per-(b,c) affine coefficients
// ---------------------------------------------------------------------------
__global__ void stats_kernel(const float* __restrict__ scale,
                             const float* __restrict__ bias) {
    int i = blockIdx.x * 256 + threadIdx.x;
    if (i < BB * CC) {
        int c = i & (CC - 1);
        float mean = g_sum[0][i] * (1.0f / T0);
        float var  = g_sum[1][i] * (1.0f / T0) - mean * mean;
        float inv  = rsqrtf(var + 1e-5f);
        float a = scale[c] * inv;
        g_coef[0][i] = a;
        g_coef[1][i] = bias[c] - mean * a;
    }
}

// ---------------------------------------------------------------------------
// apply norm+gelu -> 2 half parity planes (zero-extended)
// ---------------------------------------------------------------------------
__global__ __launch_bounds__(256) void apply_kernel(
    const float* __restrict__ h, __half* __restrict__ outH)
{
    const int bc = blockIdx.y * CC + blockIdx.x;
    const int tid = threadIdx.x;
    const float* p = h + (size_t)bc * T0;
    float a = g_coef[0][bc];
    float d = g_coef[1][bc];
    __half* ob = outH + (size_t)bc * 2 * HP1;
    for (int i = tid; i < 8008; i += 256) {
        float v = (i < T0) ? gelu_tanh(fmaf(p[i], a, d)) : 0.0f;
        ob[(size_t)(i & 1) * HP1 + (i >> 1)] = __float2half_rn(v);
    }
}

// ---------------------------------------------------------------------------
// Weight prep (all 6 layers, one launch): fp16 + m16n8k16 A-fragment order.
// ---------------------------------------------------------------------------
__global__ __launch_bounds__(256) void wprep_kernel(
    const float* __restrict__ s1, const float* __restrict__ s2,
    const float* __restrict__ s3, const float* __restrict__ s4,
    const float* __restrict__ s5, const float* __restrict__ s6,
    __half* __restrict__ dstAll)
{
    const int ly = blockIdx.y;
    const float* src = (ly == 0) ? s1 : (ly == 1) ? s2 : (ly == 2) ? s3 :
                       (ly == 3) ? s4 : (ly == 4) ? s5 : s6;
    const int K = (ly < 4) ? 3 : 2;
    size_t base = (ly <= 4) ? (size_t)ly * 786432 : (4u * 786432 + 524288);
    __half* dst = dstAll + base;
    const int total = K * 262144;

    for (int d = blockIdx.x * 256 + threadIdx.x; d < total; d += gridDim.x * 256) {
        int hh   = d & 7;
        int lane = (d >> 3) & 31;
        int cb   = (d >> 8) & 31;
        int kc   = (d >> 13) & 31;
        int j    = d >> 18;
        int q = lane >> 2, r4 = lane & 3;
        int ph = hh >> 1, off = hh & 1;
        int m = q + ((ph & 1) ? 8 : 0);
        int k = 2 * r4 + off + ((ph & 2) ? 8 : 0);
        int co = cb * 16 + m;
        int ci = kc * 16 + k;
        dst[d] = __float2half_rn(src[(size_t)(co * 512 + ci) * K + j]);
    }
}

// ---------------------------------------------------------------------------
// fp16 HMMA conv layer. CTA 128co x 128t, 8 warps (2 x 4), warp 64 x 32.
// 3-stage cp.async pipeline, 2 barriers/chunk (1 for K=2), NT=128 only.
// ---------------------------------------------------------------------------
template<int K, bool F32OUT>
__global__ __launch_bounds__(256, 2) void conv_hmma_kernel(
    const __half* __restrict__ inH, const __half* __restrict__ wh,
    void* __restrict__ outp, int HPin, int HPout, int Tout)
{
    constexpr int NT   = 128;
    constexpr int NTT  = NT / 32;              // 4
    constexpr int WU   = NT + 8;               // 136 halves per plane row
    constexpr int ABY  = K * 4096;
    constexpr int PLB  = 16 * WU * 2;          // 4352 bytes per plane
    constexpr int STGB = ABY + K * PLB;
    constexpr int NSB  = NT / 64;              // 2 B-slots per thread

    extern __shared__ char smem[];

    const int tid = threadIdx.x;
    const int wrp = tid >> 5;
    const int l   = tid & 31;
    const int q   = l >> 2;
    const int r4  = l & 3;
    const int wm  = wrp & 1;
    const int wn  = wrp >> 1;
    const int tw  = wn * (NT / 4);

    const int b   = blockIdx.z;
    const int co0 = blockIdx.y * 128;
    const int cb0 = blockIdx.y * 8;
    const int t0  = blockIdx.x * NT;

    float acc[4][NTT][4];
    #pragma unroll
    for (int mt = 0; mt < 4; ++mt)
        #pragma unroll
        for (int nt = 0; nt < NTT; ++nt)
            #pragma unroll
            for (int e = 0; e < 4; ++e) acc[mt][nt][e] = 0.0f;

    // ---- precomputed staging slots --------------------------------------
    const __half* srcA[K];
    uint32_t dA[K];
    #pragma unroll
    for (int k = 0; k < K; ++k) {
        int i = tid + k * 256;
        int j = i >> 8, x = i & 255;
        dA[k] = j * 4096 + x * 16;
        srcA[k] = wh + (size_t)(j * 32 * 32 + cb0) * 256 + x * 8;
    }
    const __half* srcB[NSB];
    uint32_t dB[NSB];
    #pragma unroll
    for (int k = 0; k < NSB; ++k) {
        int i = tid + k * 256;
        int w = i & 15, ci = (i >> 4) & 15, p = i >> 8;
        dB[k] = ABY + p * PLB + ci * (WU * 2) + w * 16;
        srcB[k] = inH + ((size_t)(b * CC + ci) * 2 + p) * HPin + t0 + 8 * w;
    }
    const __half* srcT = nullptr;
    uint32_t dT = 0;
    if (tid < 32) {
        int p = tid >> 4, ci = tid & 15;
        dT = ABY + p * PLB + ci * (WU * 2) + NT * 2;
        srcT = inH + ((size_t)(b * CC + ci) * 2 + p) * HPin + t0 + NT;
    }

    uint32_t stI = 0;
    auto issue = [&]() {
        char* SB = smem + stI;
        #pragma unroll
        for (int k = 0; k < K; ++k) {
            cp_async16(SB + dA[k], srcA[k]);
            srcA[k] += 8192;
        }
        #pragma unroll
        for (int k = 0; k < NSB; ++k) {
            cp_async16(SB + dB[k], srcB[k]);
            srcB[k] += (size_t)32 * HPin;
        }
        if (tid < 32) {
            cp_async4(SB + dT, srcT);
            srcT += (size_t)32 * HPin;
        }
        cp_commit();
        stI += STGB;
        if (stI == 3 * STGB) stI = 0;
    };

    issue();
    issue();

    const uint32_t smem_base_u = smem_u32(smem);
    uint32_t stC = 0;

    for (int c = 0; c < 32; ++c) {
        if (c < 31) cp_wait<1>(); else cp_wait<0>();
        __syncthreads();
        if (c < 30) issue();

        char* SB = smem + stC;
        const uint32_t su = smem_base_u + stC;

        if (K == 3) {
            // plane2[v] = plane0[v+1] (halves), via funnel shift on u32
            const uint32_t* p0 = (const uint32_t*)(SB + ABY);
            uint32_t* p2 = (uint32_t*)(SB + ABY + 2 * PLB);
            constexpr int HW = NT / 2;           // 64 u32 per row
            #pragma unroll
            for (int k = 0; k < 16 * HW / 256; ++k) {
                int i = tid + k * 256;
                int ci = i / HW;
                int vi = i - ci * HW;
                const uint32_t* row = p0 + ci * (WU / 2);
                uint32_t lo = row[vi], hi = row[vi + 1];
                p2[ci * (WU / 2) + vi] = __funnelshift_r(lo, hi, 16);
            }
            __syncthreads();
        }

        #pragma unroll
        for (int j = 0; j < K; ++j) {
            uint4 af[4];
            #pragma unroll
            for (int mt = 0; mt < 4; ++mt)
                af[mt] = *(const uint4*)(SB + j * 4096 + (wm * 4 + mt) * 512 + l * 16);
            #pragma unroll
            for (int nt = 0; nt < NTT; ++nt) {
                uint32_t b0, b1;
                uint32_t baddr = su + ABY + j * PLB + (l & 15) * (WU * 2)
                               + (tw + 8 * nt) * 2;
                ldmx2t(b0, b1, baddr);
                #pragma unroll
                for (int mt = 0; mt < 4; ++mt)
                    mma_f16(acc[mt][nt], (const uint32_t*)&af[mt], b0, b1);
            }
        }

        stC += STGB;
        if (stC == 3 * STGB) stC = 0;
    }
    __syncthreads();   // protect smem reuse across epilogue vs other CTA? (no reuse; cheap)

    // ---- epilogue -------------------------------------------------------
    if (F32OUT) {
        float* ob = (float*)outp;
        #pragma unroll
        for (int mt = 0; mt < 4; ++mt) {
            int row0 = co0 + wm * 64 + 16 * mt + q;
            #pragma unroll
            for (int nt = 0; nt < NTT; ++nt) {
                int t = t0 + tw + 8 * nt + 2 * r4;
                float v0 = gelu_tanh(acc[mt][nt][0]);
                float v1 = gelu_tanh(acc[mt][nt][1]);
                float v2 = gelu_tanh(acc[mt][nt][2]);
                float v3 = gelu_tanh(acc[mt][nt][3]);
                if (t < Tout) {
                    ob[(size_t)(b * CC + row0) * Tout + t]     = v0;
                    ob[(size_t)(b * CC + row0 + 8) * Tout + t] = v2;
                }
                if (t + 1 < Tout) {
                    ob[(size_t)(b * CC + row0) * Tout + t + 1]     = v1;
                    ob[(size_t)(b * CC + row0 + 8) * Tout + t + 1] = v3;
                }
            }
        }
    } else {
        __half* oh = (__half*)outp;
        #pragma unroll
        for (int mt = 0; mt < 4; ++mt) {
            int row0 = co0 + wm * 64 + 16 * mt + q;
            size_t base0 = (size_t)(b * CC + row0) * 2 * HPout;
            size_t base8 = (size_t)(b * CC + row0 + 8) * 2 * HPout;
            #pragma unroll
            for (int nt = 0; nt < NTT; ++nt) {
                int t = t0 + tw + 8 * nt + 2 * r4;   // even
                int u = t >> 1;
                __half h0 = (t     < Tout) ? __float2half_rn(gelu_tanh(acc[mt][nt][0])) : __half(0.0f);
                __half h1 = (t + 1 < Tout) ? __float2half_rn(gelu_tanh(acc[mt][nt][1])) : __half(0.0f);
                __half h2 = (t     < Tout) ? __float2half_rn(gelu_tanh(acc[mt][nt][2])) : __half(0.0f);
                __half h3 = (t + 1 < Tout) ? __float2half_rn(gelu_tanh(acc[mt][nt][3])) : __half(0.0f);
                oh[base0 + u]         = h0;
                oh[base0 + HPout + u] = h1;
                oh[base8 + u]         = h2;
                oh[base8 + HPout + u] = h3;
            }
        }
    }
}

// ---------------------------------------------------------------------------
// Tail head (reads fp32 conv6 output)
// ---------------------------------------------------------------------------
__global__ __launch_bounds__(256) void tail_kernel(
    const float* __restrict__ h, const int* __restrict__ word_ids,
    const float* __restrict__ proj_w, const float* __restrict__ proj_b,
    const float* __restrict__ cls_w1, const float* __restrict__ cls_b1,
    const float* __restrict__ cls_w2, const float* __restrict__ cls_b2,
    float* __restrict__ out)
{
    const int b = blockIdx.x;
    const int tid = threadIdx.x;
    __shared__ float feat[CC];
    __shared__ float pr[256];
    __shared__ float h1[128];

    const float* hb = h + (size_t)b * CC * T6;
    for (int c = tid; c < CC; c += 256) {
        float s = 0.0f;
        const float* row = hb + (size_t)c * T6;
        for (int t = 0; t < T6; ++t) s += row[t];
        feat[c] = s * (1.0f / (float)T6);
    }
    __syncthreads();

    {
        float s = proj_b[tid];
        const float* wrow = proj_w + (size_t)tid * CC;
        for (int d = 0; d < CC; ++d) s = fmaf(wrow[d], feat[d], s);
        pr[tid] = fmaxf(s, 0.0f);
    }
    __syncthreads();

    const int wd = word_ids[b];
    if (tid < 128) {
        float s = cls_b1[wd * 128 + tid];
        const float* w1 = cls_w1 + (size_t)wd * 256 * 128;
        for (int d = 0; d < 256; ++d)
            s = fmaf(pr[d], w1[d * 128 + tid], s);
        h1[tid] = fmaxf(s, 0.0f);
    }
    __syncthreads();

    if (tid < 5) {
        float s = cls_b2[wd * 5 + tid];
        const float* w2 = cls_w2 + (size_t)wd * 128 * 5;
        for (int d = 0; d < 128; ++d)
            s = fmaf(h1[d], w2[d * 5 + tid], s);
        out[b * 5 + tid] = s;
    }
}

// ---------------------------------------------------------------------------
// Launch
// ---------------------------------------------------------------------------
extern "C" void kernel_launch(void* const* d_in, const int* in_sizes, int n_in,
                              void* d_out, int out_size)
{
    const float* x        = (const float*)d_in[0];
    const int*   word_ids = (const int*)  d_in[1];
    const float* gn_scale = (const float*)d_in[2];
    const float* gn_bias  = (const float*)d_in[3];
    const float* proj_w   = (const float*)d_in[4];
    const float* proj_b   = (const float*)d_in[5];
    const float* cls_w1   = (const float*)d_in[6];
    const float* cls_b1   = (const float*)d_in[7];
    const float* cls_w2   = (const float*)d_in[8];
    const float* cls_b2   = (const float*)d_in[9];
    const float* w0       = (const float*)d_in[10];
    const float* w1       = (const float*)d_in[11];
    const float* w2       = (const float*)d_in[12];
    const float* w3       = (const float*)d_in[13];
    const float* w4       = (const float*)d_in[14];
    const float* w5       = (const float*)d_in[15];
    const float* w6       = (const float*)d_in[16];
    float* out = (float*)d_out;

    float *bufA = nullptr;
    __half *H1 = nullptr, *H2 = nullptr, *wrh = nullptr;
    cudaGetSymbolAddress((void**)&bufA, g_bufA);
    cudaGetSymbolAddress((void**)&H1, g_H1);
    cudaGetSymbolAddress((void**)&H2, g_H2);
    cudaGetSymbolAddress((void**)&wrh, g_wrh);

    const size_t PL3 = 786432;
    __half* wr1 = wrh;
    __half* wr2 = wr1 + PL3;
    __half* wr3 = wr2 + PL3;
    __half* wr4 = wr3 + PL3;
    __half* wr5 = wr4 + PL3;
    __half* wr6 = wr5 + 524288;

    // 3-stage smem: 3 * (K*4096 + K*16*136*2)
    const int SM3 = 3 * (3 * 4096 + 3 * 4352);   // 76032
    const int SM2 = 3 * (2 * 4096 + 2 * 4352);   // 50688
    cudaFuncSetAttribute((const void*)conv_hmma_kernel<3, false>,
                         cudaFuncAttributeMaxDynamicSharedMemorySize, SM3);
    cudaFuncSetAttribute((const void*)conv_hmma_kernel<2, false>,
                         cudaFuncAttributeMaxDynamicSharedMemorySize, SM2);
    cudaFuncSetAttribute((const void*)conv_hmma_kernel<2, true>,
                         cudaFuncAttributeMaxDynamicSharedMemorySize, SM2);

    zero_stats_kernel<<<32, 256>>>();
    wprep_kernel<<<dim3(96, 6), 256>>>(w1, w2, w3, w4, w5, w6, wrh);
    conv0_kernel<<<dim3((T0 + C0_TT - 1) / C0_TT, BB), 256>>>(x, w0, bufA);
    stats_kernel<<<32, 256>>>(gn_scale, gn_bias);
    apply_kernel<<<dim3(CC, BB), 256>>>(bufA, H1);

    conv_hmma_kernel<3, false><<<dim3(32, 4, BB), 256, SM3>>>(
        H1, wr1, H2, HP1, HP2, T1);
    conv_hmma_kernel<3, false><<<dim3(16, 4, BB), 256, SM3>>>(
        H2, wr2, H1, HP2, HP1, T2);
    conv_hmma_kernel<3, false><<<dim3(8, 4, BB), 256, SM3>>>(
        H1, wr3, H2, HP1, HP2, T3);
    conv_hmma_kernel<3, false><<<dim3(4, 4, BB), 256, SM3>>>(
        H2, wr4, H1, HP2, HP1, T4);
    conv_hmma_kernel<2, false><<<dim3(2, 4, BB), 256, SM2>>>(
        H1, wr5, H2, HP1, HP2, T5);
    conv_hmma_kernel<2, true><<<dim3(1, 4, BB), 256, SM2>>>(
        H2, wr6, bufA, HP2, 0, T6);

    tail_kernel<<<BB, 256>>>(bufA, word_ids, proj_w, proj_b,
                             cls_w1, cls_b1, cls_w2, cls_b2, out);
}